// round 16
// baseline (speedup 1.0000x reference)
#include <cuda_runtime.h>

#define N_NODES 100000
#define N_EDGES 1600000
#define D 64
#define SCAN_BLK 256
#define N_PARTIAL ((N_NODES + SCAN_BLK - 1) / SCAN_BLK)   // 391

typedef unsigned long long u64;

// Scratch (allocation-free rule: device globals)
__device__ float g_neigh[N_NODES * D];
__device__ int   g_count[N_NODES];
__device__ int   g_off[N_NODES + 1];
__device__ int   g_cursor[N_NODES];
__device__ int   g_partial[512];
__device__ u64   g_csr[N_EDGES];        // packed (w_bits << 32) | src

// ---- packed fp32x2 helpers (sm_103a FFMA2) --------------------------------
__device__ __forceinline__ void ffma2(u64& d, u64 a, u64 b) {
    asm("fma.rn.f32x2 %0, %1, %2, %0;" : "+l"(d) : "l"(a), "l"(b));
}
__device__ __forceinline__ u64 dup2(float x) {
    u64 r; asm("mov.b64 %0, {%1, %1};" : "=l"(r) : "f"(x)); return r;
}
__device__ __forceinline__ void unpack2(float& lo, float& hi, u64 v) {
    asm("mov.b64 {%0, %1}, %2;" : "=f"(lo), "=f"(hi) : "l"(v));
}

// ---------------------------------------------------------------------------
// k0: zero degree counts (+ constant tail offset)
// ---------------------------------------------------------------------------
__global__ void zero_count_kernel() {
    int i = blockIdx.x * blockDim.x + threadIdx.x;
    if (i < N_NODES) g_count[i] = 0;
    if (i == 0) g_off[N_NODES] = N_EDGES;
}

// ---------------------------------------------------------------------------
// k1: histogram of dst (fire-and-forget -> REDG)
// ---------------------------------------------------------------------------
__global__ void __launch_bounds__(256) hist_kernel(const int* __restrict__ dst) {
    int e = blockIdx.x * blockDim.x + threadIdx.x;
    if (e < N_EDGES) atomicAdd(&g_count[dst[e]], 1);
}

// ---------------------------------------------------------------------------
// k2: per-256-segment sums -> g_partial
// ---------------------------------------------------------------------------
__global__ void __launch_bounds__(256) partial_kernel() {
    __shared__ int wsum[8];
    int t = threadIdx.x;
    int idx = blockIdx.x * SCAN_BLK + t;
    int s = (idx < N_NODES) ? g_count[idx] : 0;
#pragma unroll
    for (int d = 16; d > 0; d >>= 1) s += __shfl_down_sync(0xFFFFFFFFu, s, d);
    if ((t & 31) == 0) wsum[t >> 5] = s;
    __syncthreads();
    if (t == 0) {
        int tot = 0;
#pragma unroll
        for (int w = 0; w < 8; w++) tot += wsum[w];
        g_partial[blockIdx.x] = tot;
    }
}

// ---------------------------------------------------------------------------
// k3: per-segment exclusive scan; block base via masked reduction
// ---------------------------------------------------------------------------
__global__ void __launch_bounds__(256) offsets_kernel() {
    __shared__ int wsum[8];
    __shared__ int wbase[8];
    __shared__ int sbase;
    int t = threadIdx.x;
    int lane = t & 31, wid = t >> 5;
    int bid = blockIdx.x;

    int p = 0;
    if (t < bid)       p += g_partial[t];
    if (t + 256 < bid) p += g_partial[t + 256];
#pragma unroll
    for (int d = 16; d > 0; d >>= 1) p += __shfl_down_sync(0xFFFFFFFFu, p, d);
    if (lane == 0) wsum[wid] = p;
    __syncthreads();
    if (t == 0) {
        int run = 0;
#pragma unroll
        for (int w = 0; w < 8; w++) run += wsum[w];
        sbase = run;
    }
    __syncthreads();

    int idx = bid * SCAN_BLK + t;
    int c = (idx < N_NODES) ? g_count[idx] : 0;
    int s = c;
#pragma unroll
    for (int d = 1; d < 32; d <<= 1) {
        int v = __shfl_up_sync(0xFFFFFFFFu, s, d);
        if (lane >= d) s += v;
    }
    if (lane == 31) wsum[wid] = s;
    __syncthreads();
    if (t == 0) {
        int run = 0;
#pragma unroll
        for (int w = 0; w < 8; w++) { wbase[w] = run; run += wsum[w]; }
    }
    __syncthreads();

    int excl = (s - c) + wbase[wid] + sbase;
    if (idx < N_NODES) {
        g_off[idx] = excl;
        g_cursor[idx] = excl;
    }
}

// ---------------------------------------------------------------------------
// k4: fill CSR bins — one packed 8B store per edge (atomic cursor)
// ---------------------------------------------------------------------------
__global__ void __launch_bounds__(256) fill_kernel(const int* __restrict__ src,
                                                   const int* __restrict__ dst,
                                                   const float* __restrict__ w) {
    int e = blockIdx.x * blockDim.x + threadIdx.x;
    if (e >= N_EDGES) return;
    int d = dst[e];
    int p = atomicAdd(&g_cursor[d], 1);
    g_csr[p] = ((u64)__float_as_uint(w[e]) << 32) | (unsigned)src[e];
}

// ---------------------------------------------------------------------------
// k5: gather + mean.  HALF-warp per node; lane owns 4 columns (float4).
// (R15-proven)
// ---------------------------------------------------------------------------
__global__ void __launch_bounds__(256) gather_kernel(const float4* __restrict__ feat4) {
    int half = threadIdx.x >> 4;
    int node = blockIdx.x * 16 + half;
    if (node >= N_NODES) return;
    int lane = threadIdx.x & 15;

    int beg = g_off[node];
    int end = g_off[node + 1];

    float4 a0 = make_float4(0.f, 0.f, 0.f, 0.f);
    float4 a1 = make_float4(0.f, 0.f, 0.f, 0.f);
    float4 a2 = make_float4(0.f, 0.f, 0.f, 0.f);
    float4 a3 = make_float4(0.f, 0.f, 0.f, 0.f);

    int i = beg;
    for (; i + 3 < end; i += 4) {
        u64 p0 = g_csr[i],     p1 = g_csr[i + 1];
        u64 p2 = g_csr[i + 2], p3 = g_csr[i + 3];
        float4 v0 = feat4[(long long)(unsigned)p0 * (D / 4) + lane];
        float4 v1 = feat4[(long long)(unsigned)p1 * (D / 4) + lane];
        float4 v2 = feat4[(long long)(unsigned)p2 * (D / 4) + lane];
        float4 v3 = feat4[(long long)(unsigned)p3 * (D / 4) + lane];
        float w0 = __uint_as_float((unsigned)(p0 >> 32));
        float w1 = __uint_as_float((unsigned)(p1 >> 32));
        float w2 = __uint_as_float((unsigned)(p2 >> 32));
        float w3 = __uint_as_float((unsigned)(p3 >> 32));
        a0.x += v0.x * w0; a0.y += v0.y * w0; a0.z += v0.z * w0; a0.w += v0.w * w0;
        a1.x += v1.x * w1; a1.y += v1.y * w1; a1.z += v1.z * w1; a1.w += v1.w * w1;
        a2.x += v2.x * w2; a2.y += v2.y * w2; a2.z += v2.z * w2; a2.w += v2.w * w2;
        a3.x += v3.x * w3; a3.y += v3.y * w3; a3.z += v3.z * w3; a3.w += v3.w * w3;
    }
    for (; i < end; i++) {
        u64 p0 = g_csr[i];
        float4 v0 = feat4[(long long)(unsigned)p0 * (D / 4) + lane];
        float w0 = __uint_as_float((unsigned)(p0 >> 32));
        a0.x += v0.x * w0; a0.y += v0.y * w0; a0.z += v0.z * w0; a0.w += v0.w * w0;
    }

    float rdeg = 1.0f / fmaxf((float)(end - beg), 1.0f);
    float4 r;
    r.x = ((a0.x + a1.x) + (a2.x + a3.x)) * rdeg;
    r.y = ((a0.y + a1.y) + (a2.y + a3.y)) * rdeg;
    r.z = ((a0.z + a1.z) + (a2.z + a3.z)) * rdeg;
    r.w = ((a0.w + a1.w) + (a2.w + a3.w)) * rdeg;
    ((float4*)g_neigh)[(long long)node * (D / 4) + lane] = r;
}

// ---------------------------------------------------------------------------
// k6a: self GEMM (forked stream): out = feat @ Wself^T + bias
// 128 threads, 128-node tile, 8x8/thread FFMA2; ~50 KB smem.
// ---------------------------------------------------------------------------
#define BN 130
__global__ void __launch_bounds__(128) self_gemm_kernel(
        const float* __restrict__ feat,
        const float* __restrict__ W_self,
        const float* __restrict__ bias,
        float* __restrict__ out) {
    __shared__ float featS[D][BN];
    __shared__ float WsT[D][65];
    __shared__ float biasS[D];

    const int t = threadIdx.x;
    const long long node0 = (long long)blockIdx.x * 128;

    if (t < D) biasS[t] = bias[t];

    for (int idx = t; idx < D * D; idx += 128) {
        int j = idx >> 6, k = idx & 63;
        WsT[k][j] = W_self[idx];
    }
    for (int idx = t; idx < 128 * D; idx += 128) {
        int n = idx >> 6, k = idx & 63;
        long long node = node0 + n;
        featS[k][n] = (node < N_NODES) ? feat[node * D + k] : 0.f;
    }
    __syncthreads();

    const int jg = t & 7;
    const int ng = t >> 3;

    u64 acc[4][8];
#pragma unroll
    for (int j = 0; j < 8; j++) {
        u64 b = dup2(biasS[jg + 8 * j]);
#pragma unroll
        for (int np = 0; np < 4; np++) acc[np][j] = b;
    }

#pragma unroll 4
    for (int k = 0; k < D; k++) {
        u64 a2[4];
#pragma unroll
        for (int np = 0; np < 4; np++)
            a2[np] = *reinterpret_cast<const u64*>(&featS[k][ng * 8 + 2 * np]);
        u64 bs2[8];
#pragma unroll
        for (int j = 0; j < 8; j++) bs2[j] = dup2(WsT[k][jg + 8 * j]);
#pragma unroll
        for (int np = 0; np < 4; np++)
#pragma unroll
            for (int j = 0; j < 8; j++) ffma2(acc[np][j], a2[np], bs2[j]);
    }

#pragma unroll
    for (int np = 0; np < 4; np++) {
        long long nA = node0 + ng * 8 + 2 * np;
        long long nB = nA + 1;
        bool okA = nA < N_NODES, okB = nB < N_NODES;
#pragma unroll
        for (int j = 0; j < 8; j++) {
            float lo, hi;
            unpack2(lo, hi, acc[np][j]);
            int col = jg + 8 * j;
            if (okA) out[nA * D + col] = lo;
            if (okB) out[nB * D + col] = hi;
        }
    }
}

// ---------------------------------------------------------------------------
// k6b: neighbor GEMM (joined): out += neigh @ Wneigh^T
// ---------------------------------------------------------------------------
__global__ void __launch_bounds__(128) neigh_gemm_kernel(
        const float* __restrict__ W_neigh,
        float* __restrict__ out) {
    __shared__ float neighS[D][BN];
    __shared__ float WnT[D][65];

    const int t = threadIdx.x;
    const long long node0 = (long long)blockIdx.x * 128;

    for (int idx = t; idx < D * D; idx += 128) {
        int j = idx >> 6, k = idx & 63;
        WnT[k][j] = W_neigh[idx];
    }
    for (int idx = t; idx < 128 * D; idx += 128) {
        int n = idx >> 6, k = idx & 63;
        long long node = node0 + n;
        neighS[k][n] = (node < N_NODES) ? g_neigh[node * D + k] : 0.f;
    }
    __syncthreads();

    const int jg = t & 7;
    const int ng = t >> 3;

    u64 acc[4][8];
#pragma unroll
    for (int np = 0; np < 4; np++)
#pragma unroll
        for (int j = 0; j < 8; j++) acc[np][j] = 0ull;

#pragma unroll 4
    for (int k = 0; k < D; k++) {
        u64 c2[4];
#pragma unroll
        for (int np = 0; np < 4; np++)
            c2[np] = *reinterpret_cast<const u64*>(&neighS[k][ng * 8 + 2 * np]);
        u64 bn2[8];
#pragma unroll
        for (int j = 0; j < 8; j++) bn2[j] = dup2(WnT[k][jg + 8 * j]);
#pragma unroll
        for (int np = 0; np < 4; np++)
#pragma unroll
            for (int j = 0; j < 8; j++) ffma2(acc[np][j], c2[np], bn2[j]);
    }

#pragma unroll
    for (int np = 0; np < 4; np++) {
        long long nA = node0 + ng * 8 + 2 * np;
        long long nB = nA + 1;
        bool okA = nA < N_NODES, okB = nB < N_NODES;
#pragma unroll
        for (int j = 0; j < 8; j++) {
            float lo, hi;
            unpack2(lo, hi, acc[np][j]);
            int col = jg + 8 * j;
            if (okA) out[nA * D + col] += lo;
            if (okB) out[nB * D + col] += hi;
        }
    }
}

// ---------------------------------------------------------------------------
// Launch: fork self_gemm onto a side stream (event fork/join — capture-legal),
// CSR build + gather + neigh_gemm on the main stream.
// ---------------------------------------------------------------------------
extern "C" void kernel_launch(void* const* d_in, const int* in_sizes, int n_in,
                              void* d_out, int out_size) {
    const float* feat = (const float*)d_in[0];
    const int*   src  = (const int*)d_in[1];
    const int*   dst  = (const int*)d_in[2];
    const float* ew   = (const float*)d_in[3];
    const float* Wn   = (const float*)d_in[4];
    const float* Wsf  = (const float*)d_in[5];
    const float* bias = (const float*)d_in[6];
    float* out = (float*)d_out;

    (void)in_sizes; (void)n_in; (void)out_size;

    // One-time host-object creation (streams/events are host-side, no device mem)
    static cudaStream_t s_side = nullptr;
    static cudaEvent_t  ev_fork = nullptr, ev_join = nullptr;
    if (s_side == nullptr) {
        cudaStreamCreateWithFlags(&s_side, cudaStreamNonBlocking);
        cudaEventCreateWithFlags(&ev_fork, cudaEventDisableTiming);
        cudaEventCreateWithFlags(&ev_join, cudaEventDisableTiming);
    }

    const int EB = (N_EDGES + 255) / 256;     // 6250
    const int GB = (N_NODES + 127) / 128;     // 782

    // Fork: self-GEMM is independent of the CSR pipeline.
    cudaEventRecord(ev_fork, 0);
    cudaStreamWaitEvent(s_side, ev_fork, 0);
    self_gemm_kernel<<<GB, 128, 0, s_side>>>(feat, Wsf, bias, out);
    cudaEventRecord(ev_join, s_side);

    // Main stream: CSR build + gather.
    zero_count_kernel<<<(N_NODES + 255) / 256, 256>>>();
    hist_kernel<<<EB, 256>>>(dst);
    partial_kernel<<<N_PARTIAL, 256>>>();
    offsets_kernel<<<N_PARTIAL, 256>>>();
    fill_kernel<<<EB, 256>>>(src, dst, ew);
    gather_kernel<<<(N_NODES + 15) / 16, 256>>>((const float4*)feat);

    // Join, then accumulate the neighbor transform into out.
    cudaStreamWaitEvent(0, ev_join, 0);
    neigh_gemm_kernel<<<GB, 128>>>(Wn, out);
}

// round 17
// speedup vs baseline: 1.6434x; 1.6434x over previous
#include <cuda_runtime.h>

#define N_NODES 100000
#define N_EDGES 1600000
#define D 64
#define SCAN_BLK 256
#define N_PARTIAL ((N_NODES + SCAN_BLK - 1) / SCAN_BLK)   // 391

typedef unsigned long long u64;

// Scratch (allocation-free rule: device globals)
__device__ float g_neigh[N_NODES * D];
__device__ int   g_count[N_NODES];
__device__ int   g_off[N_NODES + 1];
__device__ int   g_rank[N_EDGES];
__device__ int   g_partial[512];
__device__ u64   g_csr[N_EDGES];        // packed (w_bits << 32) | src

// ---- packed fp32x2 helpers (sm_103a FFMA2) --------------------------------
__device__ __forceinline__ void ffma2(u64& d, u64 a, u64 b) {
    asm("fma.rn.f32x2 %0, %1, %2, %0;" : "+l"(d) : "l"(a), "l"(b));
}
__device__ __forceinline__ u64 dup2(float x) {
    u64 r; asm("mov.b64 %0, {%1, %1};" : "=l"(r) : "f"(x)); return r;
}
__device__ __forceinline__ void unpack2(float& lo, float& hi, u64 v) {
    asm("mov.b64 {%0, %1}, %2;" : "=f"(lo), "=f"(hi) : "l"(v));
}

// ---------------------------------------------------------------------------
// k0: zero degree counts (+ constant tail offset)
// ---------------------------------------------------------------------------
__global__ void zero_count_kernel() {
    int i = blockIdx.x * blockDim.x + threadIdx.x;
    if (i < N_NODES) g_count[i] = 0;
    if (i == 0) g_off[N_NODES] = N_EDGES;
}

// ---------------------------------------------------------------------------
// k1: histogram of dst; the atomicAdd return value IS this edge's rank
// within its destination bin (removes the fill-side atomic entirely).
// ---------------------------------------------------------------------------
__global__ void __launch_bounds__(256) hist_kernel(const int* __restrict__ dst) {
    int e = blockIdx.x * blockDim.x + threadIdx.x;
    if (e < N_EDGES) g_rank[e] = atomicAdd(&g_count[dst[e]], 1);
}

// ---------------------------------------------------------------------------
// k2: per-256-segment sums -> g_partial
// ---------------------------------------------------------------------------
__global__ void __launch_bounds__(256) partial_kernel() {
    __shared__ int wsum[8];
    int t = threadIdx.x;
    int idx = blockIdx.x * SCAN_BLK + t;
    int s = (idx < N_NODES) ? g_count[idx] : 0;
#pragma unroll
    for (int d = 16; d > 0; d >>= 1) s += __shfl_down_sync(0xFFFFFFFFu, s, d);
    if ((t & 31) == 0) wsum[t >> 5] = s;
    __syncthreads();
    if (t == 0) {
        int tot = 0;
#pragma unroll
        for (int w = 0; w < 8; w++) tot += wsum[w];
        g_partial[blockIdx.x] = tot;
    }
}

// ---------------------------------------------------------------------------
// k3: per-segment exclusive scan; block base via masked reduction
// ---------------------------------------------------------------------------
__global__ void __launch_bounds__(256) offsets_kernel() {
    __shared__ int wsum[8];
    __shared__ int wbase[8];
    __shared__ int sbase;
    int t = threadIdx.x;
    int lane = t & 31, wid = t >> 5;
    int bid = blockIdx.x;

    int p = 0;
    if (t < bid)       p += g_partial[t];
    if (t + 256 < bid) p += g_partial[t + 256];
#pragma unroll
    for (int d = 16; d > 0; d >>= 1) p += __shfl_down_sync(0xFFFFFFFFu, p, d);
    if (lane == 0) wsum[wid] = p;
    __syncthreads();
    if (t == 0) {
        int run = 0;
#pragma unroll
        for (int w = 0; w < 8; w++) run += wsum[w];
        sbase = run;
    }
    __syncthreads();

    int idx = bid * SCAN_BLK + t;
    int c = (idx < N_NODES) ? g_count[idx] : 0;
    int s = c;
#pragma unroll
    for (int d = 1; d < 32; d <<= 1) {
        int v = __shfl_up_sync(0xFFFFFFFFu, s, d);
        if (lane >= d) s += v;
    }
    if (lane == 31) wsum[wid] = s;
    __syncthreads();
    if (t == 0) {
        int run = 0;
#pragma unroll
        for (int w = 0; w < 8; w++) { wbase[w] = run; run += wsum[w]; }
    }
    __syncthreads();

    int excl = (s - c) + wbase[wid] + sbase;
    if (idx < N_NODES) g_off[idx] = excl;
}

// ---------------------------------------------------------------------------
// k4: fill CSR bins — NO atomics: p = off[dst] + rank.  Pure streaming.
// ---------------------------------------------------------------------------
__global__ void __launch_bounds__(256) fill_kernel(const int* __restrict__ src,
                                                   const int* __restrict__ dst,
                                                   const float* __restrict__ w) {
    int e = blockIdx.x * blockDim.x + threadIdx.x;
    if (e >= N_EDGES) return;
    int p = g_off[dst[e]] + g_rank[e];
    g_csr[p] = ((u64)__float_as_uint(w[e]) << 32) | (unsigned)src[e];
}

// ---------------------------------------------------------------------------
// k5: gather + mean.  HALF-warp per node; lane owns 4 columns (float4).
// 4-edge unroll with CSR prefetch pipeline: next batch's csr words issue
// before this batch's feature loads (overlaps the two L2 latencies).
// ---------------------------------------------------------------------------
__global__ void __launch_bounds__(256) gather_kernel(const float4* __restrict__ feat4) {
    int half = threadIdx.x >> 4;
    int node = blockIdx.x * 16 + half;
    if (node >= N_NODES) return;
    int lane = threadIdx.x & 15;

    int beg = g_off[node];
    int end = g_off[node + 1];

    float4 a0 = make_float4(0.f, 0.f, 0.f, 0.f);
    float4 a1 = make_float4(0.f, 0.f, 0.f, 0.f);
    float4 a2 = make_float4(0.f, 0.f, 0.f, 0.f);
    float4 a3 = make_float4(0.f, 0.f, 0.f, 0.f);

    int i = beg;
    if (i + 3 < end) {
        int last = end - 1;
        u64 c0 = g_csr[i], c1 = g_csr[i + 1], c2 = g_csr[i + 2], c3 = g_csr[i + 3];
        for (; i + 3 < end; i += 4) {
            // prefetch next batch (index-clamped, branch-free; in-bounds)
            int j0 = min(i + 4, last), j1 = min(i + 5, last);
            int j2 = min(i + 6, last), j3 = min(i + 7, last);
            u64 n0 = g_csr[j0], n1 = g_csr[j1], n2 = g_csr[j2], n3 = g_csr[j3];

            float4 v0 = feat4[(long long)(unsigned)c0 * (D / 4) + lane];
            float4 v1 = feat4[(long long)(unsigned)c1 * (D / 4) + lane];
            float4 v2 = feat4[(long long)(unsigned)c2 * (D / 4) + lane];
            float4 v3 = feat4[(long long)(unsigned)c3 * (D / 4) + lane];
            float w0 = __uint_as_float((unsigned)(c0 >> 32));
            float w1 = __uint_as_float((unsigned)(c1 >> 32));
            float w2 = __uint_as_float((unsigned)(c2 >> 32));
            float w3 = __uint_as_float((unsigned)(c3 >> 32));
            a0.x += v0.x * w0; a0.y += v0.y * w0; a0.z += v0.z * w0; a0.w += v0.w * w0;
            a1.x += v1.x * w1; a1.y += v1.y * w1; a1.z += v1.z * w1; a1.w += v1.w * w1;
            a2.x += v2.x * w2; a2.y += v2.y * w2; a2.z += v2.z * w2; a2.w += v2.w * w2;
            a3.x += v3.x * w3; a3.y += v3.y * w3; a3.z += v3.z * w3; a3.w += v3.w * w3;

            c0 = n0; c1 = n1; c2 = n2; c3 = n3;
        }
    }
    for (; i < end; i++) {
        u64 p0 = g_csr[i];
        float4 v0 = feat4[(long long)(unsigned)p0 * (D / 4) + lane];
        float w0 = __uint_as_float((unsigned)(p0 >> 32));
        a0.x += v0.x * w0; a0.y += v0.y * w0; a0.z += v0.z * w0; a0.w += v0.w * w0;
    }

    float rdeg = 1.0f / fmaxf((float)(end - beg), 1.0f);
    float4 r;
    r.x = ((a0.x + a1.x) + (a2.x + a3.x)) * rdeg;
    r.y = ((a0.y + a1.y) + (a2.y + a3.y)) * rdeg;
    r.z = ((a0.z + a1.z) + (a2.z + a3.z)) * rdeg;
    r.w = ((a0.w + a1.w) + (a2.w + a3.w)) * rdeg;
    ((float4*)g_neigh)[(long long)node * (D / 4) + lane] = r;
}

// ---------------------------------------------------------------------------
// k6: out = feat @ Wself^T + neigh @ Wneigh^T + bias     (FFMA2 path)
// R6/R10/R15-proven: 128 threads, 128-node tile, 8x8/thread, ~100 KB smem.
// ---------------------------------------------------------------------------
#define BN 130
__global__ void __launch_bounds__(128) out_kernel(
        const float* __restrict__ feat,
        const float* __restrict__ W_neigh,
        const float* __restrict__ W_self,
        const float* __restrict__ bias,
        float* __restrict__ out) {
    __shared__ float featS[D][BN];
    __shared__ float neighS[D][BN];
    __shared__ float WsT[D][65];
    __shared__ float WnT[D][65];
    __shared__ float biasS[D];

    const int t = threadIdx.x;
    const long long node0 = (long long)blockIdx.x * 128;

    if (t < D) biasS[t] = bias[t];

    for (int idx = t; idx < D * D; idx += 128) {
        int j = idx >> 6, k = idx & 63;
        WsT[k][j] = W_self[idx];
        WnT[k][j] = W_neigh[idx];
    }
    for (int idx = t; idx < 128 * D; idx += 128) {
        int n = idx >> 6, k = idx & 63;
        long long node = node0 + n;
        float fv = 0.f, nv = 0.f;
        if (node < N_NODES) {
            fv = feat[node * D + k];
            nv = g_neigh[node * D + k];
        }
        featS[k][n]  = fv;
        neighS[k][n] = nv;
    }
    __syncthreads();

    const int jg = t & 7;    // cols jg + 8*j
    const int ng = t >> 3;   // nodes ng*8 .. ng*8+7

    u64 acc[4][8];
#pragma unroll
    for (int j = 0; j < 8; j++) {
        u64 b = dup2(biasS[jg + 8 * j]);
#pragma unroll
        for (int np = 0; np < 4; np++) acc[np][j] = b;
    }

#pragma unroll 2
    for (int k = 0; k < D; k++) {
        u64 a2[4], c2[4];
#pragma unroll
        for (int np = 0; np < 4; np++) {
            a2[np] = *reinterpret_cast<const u64*>(&featS[k][ng * 8 + 2 * np]);
            c2[np] = *reinterpret_cast<const u64*>(&neighS[k][ng * 8 + 2 * np]);
        }
        u64 bs2[8], bn2[8];
#pragma unroll
        for (int j = 0; j < 8; j++) {
            bs2[j] = dup2(WsT[k][jg + 8 * j]);
            bn2[j] = dup2(WnT[k][jg + 8 * j]);
        }
#pragma unroll
        for (int np = 0; np < 4; np++)
#pragma unroll
            for (int j = 0; j < 8; j++) {
                ffma2(acc[np][j], a2[np], bs2[j]);
                ffma2(acc[np][j], c2[np], bn2[j]);
            }
    }

#pragma unroll
    for (int np = 0; np < 4; np++) {
        long long nA = node0 + ng * 8 + 2 * np;
        long long nB = nA + 1;
        bool okA = nA < N_NODES, okB = nB < N_NODES;
#pragma unroll
        for (int j = 0; j < 8; j++) {
            float lo, hi;
            unpack2(lo, hi, acc[np][j]);
            int col = jg + 8 * j;
            if (okA) out[nA * D + col] = lo;
            if (okB) out[nB * D + col] = hi;
        }
    }
}

// ---------------------------------------------------------------------------
// Launch (single stream — fork/join regressed under this harness's capture)
// ---------------------------------------------------------------------------
extern "C" void kernel_launch(void* const* d_in, const int* in_sizes, int n_in,
                              void* d_out, int out_size) {
    const float* feat = (const float*)d_in[0];
    const int*   src  = (const int*)d_in[1];
    const int*   dst  = (const int*)d_in[2];
    const float* ew   = (const float*)d_in[3];
    const float* Wn   = (const float*)d_in[4];
    const float* Wsf  = (const float*)d_in[5];
    const float* bias = (const float*)d_in[6];
    float* out = (float*)d_out;

    (void)in_sizes; (void)n_in; (void)out_size;

    const int EB = (N_EDGES + 255) / 256;     // 6250

    zero_count_kernel<<<(N_NODES + 255) / 256, 256>>>();
    hist_kernel<<<EB, 256>>>(dst);
    partial_kernel<<<N_PARTIAL, 256>>>();
    offsets_kernel<<<N_PARTIAL, 256>>>();
    fill_kernel<<<EB, 256>>>(src, dst, ew);
    gather_kernel<<<(N_NODES + 15) / 16, 256>>>((const float4*)feat);
    out_kernel<<<(N_NODES + 127) / 128, 128>>>(feat, Wn, Wsf, bias, out);
}